// round 12
// baseline (speedup 1.0000x reference)
#include <cuda_runtime.h>
#include <cstdint>
#include <cstddef>

// ============================================================================
// Problem dims
// ============================================================================
#define S_DIM   512
#define R_DIM   384
#define C_MSA   64
#define C_OUTER 32
#define C_OUT   128

#define M1 (R_DIM * C_OUTER)       // 12288
#define K1 S_DIM                   // 512
#define M2 (R_DIM * R_DIM)         // 147456
#define K2 (C_OUTER * C_OUTER)     // 1024

// ============================================================================
// Device-global scratch (allocation-free per harness rules)
// ============================================================================
__device__ float g_leftT [(size_t)M1 * K1];     // [(r*32+c), s] tf32-rounded
__device__ float g_rightT[(size_t)M1 * K1];     // [(r*32+e), s] tf32-rounded
__device__ float g_outer [(size_t)M2 * K2];     // [(b*384+d), c*32+e] tf32-rounded
__device__ float g_Wt    [(size_t)C_OUT * K2];  // [f, c*32+e] tf32-rounded
__device__ float g_norm  [(size_t)R_DIM * R_DIM];

// ============================================================================
// Helpers
// ============================================================================
__device__ __forceinline__ uint32_t smem_u32(const void* p) {
    uint32_t a;
    asm("{ .reg .u64 t; cvta.to.shared.u64 t, %1; cvt.u32.u64 %0, t; }"
        : "=r"(a) : "l"(p));
    return a;
}

// tf32 round-to-nearest: .b32 destination (returns bit pattern)
__device__ __forceinline__ uint32_t tf32_bits(float x) {
    uint32_t r;
    asm("cvt.rna.tf32.f32 %0, %1;" : "=r"(r) : "f"(x));
    return r;
}
__device__ __forceinline__ float rn_tf32(float x) {
    return __uint_as_float(tf32_bits(x));
}

__device__ __forceinline__ void cp16(uint32_t dst_smem, const void* src) {
    asm volatile("cp.async.cg.shared.global [%0], [%1], 16;"
                 :: "r"(dst_smem), "l"(src) : "memory");
}
#define CP_ASYNC_COMMIT() asm volatile("cp.async.commit_group;" ::: "memory")
#define CP_ASYNC_WAIT(n)  asm volatile("cp.async.wait_group %0;" :: "n"(n) : "memory")

// mma.sync m16n8k8 tf32: D += A*B, A row-major 16x8(K), B col-major 8(K)x8
#define MMA_TF32(d, a, b) \
    asm volatile( \
        "mma.sync.aligned.m16n8k8.row.col.f32.tf32.tf32.f32 " \
        "{%0,%1,%2,%3}, {%4,%5,%6,%7}, {%8,%9}, {%0,%1,%2,%3};" \
        : "+f"((d)[0]), "+f"((d)[1]), "+f"((d)[2]), "+f"((d)[3]) \
        : "r"((a)[0]), "r"((a)[1]), "r"((a)[2]), "r"((a)[3]), \
          "r"((b)[0]), "r"((b)[1]))

__device__ __forceinline__ uint32_t f2u(float x) { return __float_as_uint(x); }

// ============================================================================
// Kernel: LayerNorm + projections + mask -> leftT/rightT (K-major tf32)
// grid (4, 384), block 128
// ============================================================================
__global__ __launch_bounds__(128)
void ln_proj_kernel(const float* __restrict__ msa, const float* __restrict__ mask,
                    const float* __restrict__ gamma, const float* __restrict__ beta,
                    const float* __restrict__ wl, const float* __restrict__ wr)
{
    __shared__ float s_wl[C_OUTER][C_MSA];
    __shared__ float s_wr[C_OUTER][C_MSA];
    __shared__ float s_g[C_MSA], s_b[C_MSA];

    const int t = threadIdx.x;
    for (int i = t; i < C_OUTER * C_MSA; i += 128) {
        s_wl[i >> 6][i & 63] = wl[i];
        s_wr[i >> 6][i & 63] = wr[i];
    }
    if (t < C_MSA) { s_g[t] = gamma[t]; s_b[t] = beta[t]; }
    __syncthreads();

    const int r = blockIdx.y;
    const int s = blockIdx.x * 128 + t;

    const float* mrow = msa + ((size_t)s * R_DIM + r) * C_MSA;
    float x[C_MSA];
    #pragma unroll
    for (int i = 0; i < C_MSA / 4; i++) {
        float4 v = reinterpret_cast<const float4*>(mrow)[i];
        x[4*i+0] = v.x; x[4*i+1] = v.y; x[4*i+2] = v.z; x[4*i+3] = v.w;
    }
    float s1 = 0.f, s2 = 0.f;
    #pragma unroll
    for (int c = 0; c < C_MSA; c++) { s1 += x[c]; s2 += x[c] * x[c]; }
    const float mu = s1 * (1.0f / C_MSA);
    const float var = s2 * (1.0f / C_MSA) - mu * mu;
    const float rs = rsqrtf(var + 1e-5f);
    const float mk = mask[(size_t)s * R_DIM + r];
    #pragma unroll
    for (int c = 0; c < C_MSA; c++)
        x[c] = ((x[c] - mu) * rs * s_g[c] + s_b[c]) * mk;  // fold mask

    for (int o = 0; o < C_OUTER; o++) {
        float dl = 0.f, dr = 0.f;
        #pragma unroll
        for (int c = 0; c < C_MSA; c++) {
            dl += x[c] * s_wl[o][c];
            dr += x[c] * s_wr[o][c];
        }
        g_leftT [((size_t)(r * C_OUTER + o)) * K1 + s] = rn_tf32(dl);
        g_rightT[((size_t)(r * C_OUTER + o)) * K1 + s] = rn_tf32(dr);
    }
}

// ============================================================================
// Kernel: transpose/round output_w [c][e][f] -> Wt [f][c*32+e]
// ============================================================================
__global__ __launch_bounds__(256)
void wt_prep_kernel(const float* __restrict__ ow)
{
    int idx = blockIdx.x * 256 + threadIdx.x;       // f-major linear
    int f = idx >> 10, ce = idx & 1023;
    g_Wt[idx] = rn_tf32(ow[(size_t)ce * C_OUT + f]);
}

// ============================================================================
// Kernel: norm[b][d] = sum_s mask[s][b] * mask[s][d]
// ============================================================================
__global__ __launch_bounds__(384)
void norm_kernel(const float* __restrict__ mask)
{
    __shared__ float rowv[R_DIM];
    const int t = threadIdx.x;
    const int b0 = blockIdx.x * 8;
    float acc[8] = {0, 0, 0, 0, 0, 0, 0, 0};
    for (int s = 0; s < S_DIM; s++) {
        __syncthreads();
        rowv[t] = mask[(size_t)s * R_DIM + t];
        __syncthreads();
        const float md = rowv[t];
        #pragma unroll
        for (int j = 0; j < 8; j++) acc[j] += rowv[b0 + j] * md;
    }
    #pragma unroll
    for (int j = 0; j < 8; j++)
        g_norm[(size_t)(b0 + j) * R_DIM + t] = acc[j];
}

// ============================================================================
// GEMM tile config: BM=256, BN=128, BK=32; 256 thr = 8 warps (4M x 2N),
// warp tile 64x64 (mi=4, ni=8).  3-stage cp.async pipeline, ONE sync/chunk,
// prefetch issued BEFORE compute. 1 CTA/SM (~254 regs). Rows padded to 36 fl.
// ============================================================================
#define BK        32
#define ROWF      36
#define AF        (256 * ROWF)                 // A tile floats (9216)
#define BF        (128 * ROWF)                 // B tile floats (4608)
#define STAGEF    (AF + BF)                    // 13824 floats per stage
#define NSTAGE    3
#define GSMEM     (NSTAGE * STAGEF * 4)        // 165888 bytes

// load a ROWS x 32 tile (row-major K) with 256 threads
template <int ROWS>
__device__ __forceinline__ void load_tile(uint32_t sbuf, const float* gbase,
                                          int row0, int ldk, int kof)
{
    const int tid = threadIdx.x;
    #pragma unroll
    for (int k = 0; k < ROWS / 32; k++) {
        int u = k * 256 + tid;
        int row = u >> 3, seg = u & 7;
        const float* src = gbase + ((size_t)(row0 + row)) * ldk + kof + seg * 4;
        cp16(sbuf + row * 144 + seg * 16, src);
    }
}

// compute one BK chunk: acc[4][8][4] += A_tile(256x32) x B_tile(128x32)^T
__device__ __forceinline__ void mma_chunk(const float* __restrict__ A,
                                          const float* __restrict__ B,
                                          int wm, int wn, int lane,
                                          float acc[4][8][4])
{
    const int lr = lane >> 2;      // 0..7
    const int lc = lane & 3;       // 0..3
    #pragma unroll
    for (int kk = 0; kk < 4; kk++) {
        const int c0 = kk * 8 + lc;
        uint32_t a[4][4], b[8][2];
        #pragma unroll
        for (int mi = 0; mi < 4; mi++) {
            const int r0 = wm * 64 + mi * 16 + lr;
            a[mi][0] = f2u(A[r0 * ROWF + c0]);
            a[mi][1] = f2u(A[(r0 + 8) * ROWF + c0]);
            a[mi][2] = f2u(A[r0 * ROWF + c0 + 4]);
            a[mi][3] = f2u(A[(r0 + 8) * ROWF + c0 + 4]);
        }
        #pragma unroll
        for (int ni = 0; ni < 8; ni++) {
            const int rb = wn * 64 + ni * 8 + lr;
            b[ni][0] = f2u(B[rb * ROWF + c0]);
            b[ni][1] = f2u(B[rb * ROWF + c0 + 4]);
        }
        #pragma unroll
        for (int mi = 0; mi < 4; mi++)
            #pragma unroll
            for (int ni = 0; ni < 8; ni++)
                MMA_TF32(acc[mi][ni], a[mi], b[ni]);
    }
}

// ============================================================================
// GEMM1: outer = leftT (12288x512) x rightT^T (12288x512) -> scatter
// grid (96, 48), block 256
// ============================================================================
__global__ __launch_bounds__(256, 1)
void gemm1_kernel()
{
    extern __shared__ __align__(16) float smem[];
    const int tid = threadIdx.x;
    const int lane = tid & 31;
    const int wid = tid >> 5;
    const int wm = wid >> 1, wn = wid & 1;
    const int m0 = blockIdx.y * 256;   // bc
    const int n0 = blockIdx.x * 128;   // de

    float acc[4][8][4] = {};

    // Prologue: stages 0,1 in flight
    #pragma unroll
    for (int s = 0; s < 2; s++) {
        uint32_t sb = smem_u32(smem + s * STAGEF);
        load_tile<256>(sb,          g_leftT,  m0, K1, s * BK);
        load_tile<128>(sb + AF * 4, g_rightT, n0, K1, s * BK);
        CP_ASYNC_COMMIT();
    }

    const int NCH = K1 / BK;   // 16
    for (int i = 0; i < NCH; i++) {
        if (i == NCH - 1) { CP_ASYNC_WAIT(0); } else { CP_ASYNC_WAIT(1); }
        __syncthreads();
        // Prefetch chunk i+2 FIRST (overlaps STS with the MMAs below);
        // its buffer was last read at iter i-1, protected by the barrier above.
        if (i + 2 < NCH) {
            uint32_t sb = smem_u32(smem + ((i + 2) % NSTAGE) * STAGEF);
            load_tile<256>(sb,          g_leftT,  m0, K1, (i + 2) * BK);
            load_tile<128>(sb + AF * 4, g_rightT, n0, K1, (i + 2) * BK);
            CP_ASYNC_COMMIT();
        }
        const float* As = smem + (i % NSTAGE) * STAGEF;
        const float* Bs = As + AF;
        mma_chunk(As, Bs, wm, wn, lane, acc);
    }

    // Epilogue: scatter (bc, de) tile -> outer[(b*384+d)*1024 + c*32+e]
    const int lr = lane >> 2, lc = lane & 3;
    #pragma unroll
    for (int mi = 0; mi < 4; mi++) {
        #pragma unroll
        for (int ni = 0; ni < 8; ni++) {
            const int m = m0 + wm * 64 + mi * 16 + lr;
            const int n = n0 + wn * 64 + ni * 8 + 2 * lc;
            const int b = m >> 5, c = m & 31;
            const int d = n >> 5, e = n & 31;
            float2 v0 = { rn_tf32(acc[mi][ni][0]), rn_tf32(acc[mi][ni][1]) };
            float2 v1 = { rn_tf32(acc[mi][ni][2]), rn_tf32(acc[mi][ni][3]) };
            float* base = g_outer + ((size_t)(b * R_DIM + d)) * K2 + e;
            __stcs(reinterpret_cast<float2*>(base + c * 32), v0);
            __stcs(reinterpret_cast<float2*>(base + (c + 8) * 32), v1);
        }
    }
}

// ============================================================================
// GEMM2: act = outer (147456x1024) x Wt^T (128x1024), fused bias+norm
// grid 576, block 256
// ============================================================================
__global__ __launch_bounds__(256, 1)
void gemm2_kernel(float* __restrict__ out, const float* __restrict__ bias)
{
    extern __shared__ __align__(16) float smem[];
    const int tid = threadIdx.x;
    const int lane = tid & 31;
    const int wid = tid >> 5;
    const int wm = wid >> 1, wn = wid & 1;
    const int m0 = blockIdx.x * 256;   // bd

    float acc[4][8][4] = {};

    #pragma unroll
    for (int s = 0; s < 2; s++) {
        uint32_t sb = smem_u32(smem + s * STAGEF);
        load_tile<256>(sb,          g_outer, m0, K2, s * BK);
        load_tile<128>(sb + AF * 4, g_Wt,    0,  K2, s * BK);
        CP_ASYNC_COMMIT();
    }

    const int NCH = K2 / BK;   // 32
    for (int i = 0; i < NCH; i++) {
        if (i == NCH - 1) { CP_ASYNC_WAIT(0); } else { CP_ASYNC_WAIT(1); }
        __syncthreads();
        if (i + 2 < NCH) {
            uint32_t sb = smem_u32(smem + ((i + 2) % NSTAGE) * STAGEF);
            load_tile<256>(sb,          g_outer, m0, K2, (i + 2) * BK);
            load_tile<128>(sb + AF * 4, g_Wt,    0,  K2, (i + 2) * BK);
            CP_ASYNC_COMMIT();
        }
        const float* As = smem + (i % NSTAGE) * STAGEF;
        const float* Bs = As + AF;
        mma_chunk(As, Bs, wm, wn, lane, acc);
    }

    const int lr = lane >> 2, lc = lane & 3;
    #pragma unroll
    for (int mi = 0; mi < 4; mi++) {
        const int m = m0 + wm * 64 + mi * 16 + lr;
        const float rn0 = 1.0f / (1e-3f + g_norm[m]);
        const float rn1 = 1.0f / (1e-3f + g_norm[m + 8]);
        #pragma unroll
        for (int ni = 0; ni < 8; ni++) {
            const int f = wn * 64 + ni * 8 + 2 * lc;
            const float b0 = __ldg(bias + f), b1 = __ldg(bias + f + 1);
            float2 v0 = { (acc[mi][ni][0] + b0) * rn0, (acc[mi][ni][1] + b1) * rn0 };
            float2 v1 = { (acc[mi][ni][2] + b0) * rn1, (acc[mi][ni][3] + b1) * rn1 };
            __stcs(reinterpret_cast<float2*>(out + (size_t)m * C_OUT + f), v0);
            __stcs(reinterpret_cast<float2*>(out + (size_t)(m + 8) * C_OUT + f), v1);
        }
    }
}

// ============================================================================
// Launch
// ============================================================================
extern "C" void kernel_launch(void* const* d_in, const int* in_sizes, int n_in,
                              void* d_out, int out_size)
{
    const float* msa   = (const float*)d_in[0];
    const float* mask  = (const float*)d_in[1];
    const float* gamma = (const float*)d_in[2];
    const float* beta  = (const float*)d_in[3];
    const float* wl    = (const float*)d_in[4];
    const float* wr    = (const float*)d_in[5];
    const float* ow    = (const float*)d_in[6];
    const float* ob    = (const float*)d_in[7];
    float* out = (float*)d_out;

    cudaFuncSetAttribute(gemm1_kernel,
                         cudaFuncAttributeMaxDynamicSharedMemorySize, GSMEM);
    cudaFuncSetAttribute(gemm2_kernel,
                         cudaFuncAttributeMaxDynamicSharedMemorySize, GSMEM);

    ln_proj_kernel<<<dim3(S_DIM / 128, R_DIM), 128>>>(msa, mask, gamma, beta, wl, wr);
    wt_prep_kernel<<<(C_OUT * K2) / 256, 256>>>(ow);
    norm_kernel<<<R_DIM / 8, R_DIM>>>(mask);
    gemm1_kernel<<<dim3(M1 / 128, M1 / 256), 256, GSMEM>>>();
    gemm2_kernel<<<M2 / 256, 256, GSMEM>>>(out, ob);
}

// round 13
// speedup vs baseline: 1.0254x; 1.0254x over previous
#include <cuda_runtime.h>
#include <cstdint>
#include <cstddef>

// ============================================================================
// Problem dims
// ============================================================================
#define S_DIM   512
#define R_DIM   384
#define C_MSA   64
#define C_OUTER 32
#define C_OUT   128

#define M1 (R_DIM * C_OUTER)       // 12288
#define K1 S_DIM                   // 512
#define M2 (R_DIM * R_DIM)         // 147456
#define K2 (C_OUTER * C_OUTER)     // 1024

// ============================================================================
// Device-global scratch (allocation-free per harness rules)
// ============================================================================
__device__ float g_leftT [(size_t)M1 * K1];     // [(r*32+c), s] tf32-rounded
__device__ float g_rightT[(size_t)M1 * K1];     // [(r*32+e), s] tf32-rounded
__device__ float g_outer [(size_t)M2 * K2];     // [(b*384+d), c*32+e] tf32-rounded
__device__ float g_Wt    [(size_t)C_OUT * K2];  // [f, c*32+e] tf32-rounded
__device__ float g_norm  [(size_t)R_DIM * R_DIM];

// ============================================================================
// Helpers
// ============================================================================
__device__ __forceinline__ uint32_t smem_u32(const void* p) {
    uint32_t a;
    asm("{ .reg .u64 t; cvta.to.shared.u64 t, %1; cvt.u32.u64 %0, t; }"
        : "=r"(a) : "l"(p));
    return a;
}

// tf32 round-to-nearest: .b32 destination (returns bit pattern)
__device__ __forceinline__ uint32_t tf32_bits(float x) {
    uint32_t r;
    asm("cvt.rna.tf32.f32 %0, %1;" : "=r"(r) : "f"(x));
    return r;
}
__device__ __forceinline__ float rn_tf32(float x) {
    return __uint_as_float(tf32_bits(x));
}

__device__ __forceinline__ void cp16(uint32_t dst_smem, const void* src) {
    asm volatile("cp.async.cg.shared.global [%0], [%1], 16;"
                 :: "r"(dst_smem), "l"(src) : "memory");
}
#define CP_ASYNC_COMMIT() asm volatile("cp.async.commit_group;" ::: "memory")
#define CP_ASYNC_WAIT(n)  asm volatile("cp.async.wait_group %0;" :: "n"(n) : "memory")

// mma.sync m16n8k8 tf32: D += A*B, A row-major 16x8(K), B col-major 8(K)x8
#define MMA_TF32(d, a, b) \
    asm volatile( \
        "mma.sync.aligned.m16n8k8.row.col.f32.tf32.tf32.f32 " \
        "{%0,%1,%2,%3}, {%4,%5,%6,%7}, {%8,%9}, {%0,%1,%2,%3};" \
        : "+f"((d)[0]), "+f"((d)[1]), "+f"((d)[2]), "+f"((d)[3]) \
        : "r"((a)[0]), "r"((a)[1]), "r"((a)[2]), "r"((a)[3]), \
          "r"((b)[0]), "r"((b)[1]))

__device__ __forceinline__ uint32_t f2u(float x) { return __float_as_uint(x); }

// ============================================================================
// Kernel: LayerNorm + projections + mask -> leftT/rightT (K-major tf32)
// grid (4, 384), block 128
// ============================================================================
__global__ __launch_bounds__(128)
void ln_proj_kernel(const float* __restrict__ msa, const float* __restrict__ mask,
                    const float* __restrict__ gamma, const float* __restrict__ beta,
                    const float* __restrict__ wl, const float* __restrict__ wr)
{
    __shared__ float s_wl[C_OUTER][C_MSA];
    __shared__ float s_wr[C_OUTER][C_MSA];
    __shared__ float s_g[C_MSA], s_b[C_MSA];

    const int t = threadIdx.x;
    for (int i = t; i < C_OUTER * C_MSA; i += 128) {
        s_wl[i >> 6][i & 63] = wl[i];
        s_wr[i >> 6][i & 63] = wr[i];
    }
    if (t < C_MSA) { s_g[t] = gamma[t]; s_b[t] = beta[t]; }
    __syncthreads();

    const int r = blockIdx.y;
    const int s = blockIdx.x * 128 + t;

    const float* mrow = msa + ((size_t)s * R_DIM + r) * C_MSA;
    float x[C_MSA];
    #pragma unroll
    for (int i = 0; i < C_MSA / 4; i++) {
        float4 v = reinterpret_cast<const float4*>(mrow)[i];
        x[4*i+0] = v.x; x[4*i+1] = v.y; x[4*i+2] = v.z; x[4*i+3] = v.w;
    }
    float s1 = 0.f, s2 = 0.f;
    #pragma unroll
    for (int c = 0; c < C_MSA; c++) { s1 += x[c]; s2 += x[c] * x[c]; }
    const float mu = s1 * (1.0f / C_MSA);
    const float var = s2 * (1.0f / C_MSA) - mu * mu;
    const float rs = rsqrtf(var + 1e-5f);
    const float mk = mask[(size_t)s * R_DIM + r];
    #pragma unroll
    for (int c = 0; c < C_MSA; c++)
        x[c] = ((x[c] - mu) * rs * s_g[c] + s_b[c]) * mk;  // fold mask

    for (int o = 0; o < C_OUTER; o++) {
        float dl = 0.f, dr = 0.f;
        #pragma unroll
        for (int c = 0; c < C_MSA; c++) {
            dl += x[c] * s_wl[o][c];
            dr += x[c] * s_wr[o][c];
        }
        g_leftT [((size_t)(r * C_OUTER + o)) * K1 + s] = rn_tf32(dl);
        g_rightT[((size_t)(r * C_OUTER + o)) * K1 + s] = rn_tf32(dr);
    }
}

// ============================================================================
// Kernel: transpose/round output_w [c][e][f] -> Wt [f][c*32+e]
// ============================================================================
__global__ __launch_bounds__(256)
void wt_prep_kernel(const float* __restrict__ ow)
{
    int idx = blockIdx.x * 256 + threadIdx.x;       // f-major linear
    int f = idx >> 10, ce = idx & 1023;
    g_Wt[idx] = rn_tf32(ow[(size_t)ce * C_OUT + f]);
}

// ============================================================================
// Kernel: norm[b][d] = sum_s mask[s][b] * mask[s][d]
// ============================================================================
__global__ __launch_bounds__(384)
void norm_kernel(const float* __restrict__ mask)
{
    __shared__ float rowv[R_DIM];
    const int t = threadIdx.x;
    const int b0 = blockIdx.x * 8;
    float acc[8] = {0, 0, 0, 0, 0, 0, 0, 0};
    for (int s = 0; s < S_DIM; s++) {
        __syncthreads();
        rowv[t] = mask[(size_t)s * R_DIM + t];
        __syncthreads();
        const float md = rowv[t];
        #pragma unroll
        for (int j = 0; j < 8; j++) acc[j] += rowv[b0 + j] * md;
    }
    #pragma unroll
    for (int j = 0; j < 8; j++)
        g_norm[(size_t)(b0 + j) * R_DIM + t] = acc[j];
}

// ============================================================================
// GEMM tile config: BM=BN=128, BK=32, 256 thr = 8 warps (4M x 2N),
// warp tile 32x64 (mi=2, ni=8).  3-stage cp.async pipeline, ONE sync/chunk,
// prefetch issued BEFORE compute (STS overlaps MMA).
// smem rows padded to 36 floats (conflict-free fragment LDS).
// ============================================================================
#define BK        32
#define ROWF      36
#define TILEF     (128 * ROWF)                 // 4608 floats per tile
#define STAGEF    (2 * TILEF)                  // A + B per stage
#define NSTAGE    3
#define GSMEM     (NSTAGE * STAGEF * 4)        // 110592 bytes

// load one 128x32 tile (row-major K) from gbase[(row0+row)*ldk + kof ..]
__device__ __forceinline__ void load_tile(uint32_t sbuf, const float* gbase,
                                          int row0, int ldk, int kof)
{
    const int tid = threadIdx.x;
    #pragma unroll
    for (int k = 0; k < 4; k++) {
        int u = k * 256 + tid;
        int row = u >> 3, seg = u & 7;
        const float* src = gbase + ((size_t)(row0 + row)) * ldk + kof + seg * 4;
        cp16(sbuf + row * 144 + seg * 16, src);
    }
}

// compute one BK chunk: acc[2][8][4] += A_tile x B_tile
__device__ __forceinline__ void mma_chunk(const float* __restrict__ A,
                                          const float* __restrict__ B,
                                          int wm, int wn, int lane,
                                          float acc[2][8][4])
{
    const int lr = lane >> 2;      // 0..7
    const int lc = lane & 3;       // 0..3
    #pragma unroll
    for (int kk = 0; kk < 4; kk++) {
        const int c0 = kk * 8 + lc;
        uint32_t a[2][4], b[8][2];
        #pragma unroll
        for (int mi = 0; mi < 2; mi++) {
            const int r0 = wm * 32 + mi * 16 + lr;
            a[mi][0] = f2u(A[r0 * ROWF + c0]);
            a[mi][1] = f2u(A[(r0 + 8) * ROWF + c0]);
            a[mi][2] = f2u(A[r0 * ROWF + c0 + 4]);
            a[mi][3] = f2u(A[(r0 + 8) * ROWF + c0 + 4]);
        }
        #pragma unroll
        for (int ni = 0; ni < 8; ni++) {
            const int rb = wn * 64 + ni * 8 + lr;
            b[ni][0] = f2u(B[rb * ROWF + c0]);
            b[ni][1] = f2u(B[rb * ROWF + c0 + 4]);
        }
        #pragma unroll
        for (int mi = 0; mi < 2; mi++)
            #pragma unroll
            for (int ni = 0; ni < 8; ni++)
                MMA_TF32(acc[mi][ni], a[mi], b[ni]);
    }
}

// ============================================================================
// GEMM1: outer = leftT (12288x512) x rightT^T (12288x512) -> scatter
// grid (96, 96), block 256
// ============================================================================
__global__ __launch_bounds__(256, 2)
void gemm1_kernel()
{
    extern __shared__ __align__(16) float smem[];
    const int tid = threadIdx.x;
    const int lane = tid & 31;
    const int wid = tid >> 5;
    const int wm = wid >> 1, wn = wid & 1;
    const int m0 = blockIdx.y * 128;   // bc
    const int n0 = blockIdx.x * 128;   // de

    float acc[2][8][4] = {};

    // Prologue: stages 0,1 in flight
    #pragma unroll
    for (int s = 0; s < 2; s++) {
        uint32_t sb = smem_u32(smem + s * STAGEF);
        load_tile(sb,             g_leftT,  m0, K1, s * BK);
        load_tile(sb + TILEF * 4, g_rightT, n0, K1, s * BK);
        CP_ASYNC_COMMIT();
    }

    const int NCH = K1 / BK;   // 16
    for (int i = 0; i < NCH; i++) {
        if (i == NCH - 1) { CP_ASYNC_WAIT(0); } else { CP_ASYNC_WAIT(1); }
        __syncthreads();
        // Prefetch chunk i+2 FIRST so its STS overlaps the MMAs below.
        // Its buffer was last read at iter i-1, protected by the barrier above.
        if (i + 2 < NCH) {
            uint32_t sb = smem_u32(smem + ((i + 2) % NSTAGE) * STAGEF);
            load_tile(sb,             g_leftT,  m0, K1, (i + 2) * BK);
            load_tile(sb + TILEF * 4, g_rightT, n0, K1, (i + 2) * BK);
            CP_ASYNC_COMMIT();
        }
        const float* As = smem + (i % NSTAGE) * STAGEF;
        const float* Bs = As + TILEF;
        mma_chunk(As, Bs, wm, wn, lane, acc);
    }

    // Epilogue: scatter (bc, de) tile -> outer[(b*384+d)*1024 + c*32+e]
    const int lr = lane >> 2, lc = lane & 3;
    #pragma unroll
    for (int mi = 0; mi < 2; mi++) {
        #pragma unroll
        for (int ni = 0; ni < 8; ni++) {
            const int m = m0 + wm * 32 + mi * 16 + lr;
            const int n = n0 + wn * 64 + ni * 8 + 2 * lc;
            const int b = m >> 5, c = m & 31;
            const int d = n >> 5, e = n & 31;
            float2 v0 = { rn_tf32(acc[mi][ni][0]), rn_tf32(acc[mi][ni][1]) };
            float2 v1 = { rn_tf32(acc[mi][ni][2]), rn_tf32(acc[mi][ni][3]) };
            float* base = g_outer + ((size_t)(b * R_DIM + d)) * K2 + e;
            __stcs(reinterpret_cast<float2*>(base + c * 32), v0);
            __stcs(reinterpret_cast<float2*>(base + (c + 8) * 32), v1);
        }
    }
}

// ============================================================================
// GEMM2: act = outer (147456x1024) x Wt^T (128x1024), fused bias+norm
// grid 1152, block 256
// ============================================================================
__global__ __launch_bounds__(256, 2)
void gemm2_kernel(float* __restrict__ out, const float* __restrict__ bias)
{
    extern __shared__ __align__(16) float smem[];
    const int tid = threadIdx.x;
    const int lane = tid & 31;
    const int wid = tid >> 5;
    const int wm = wid >> 1, wn = wid & 1;
    const int m0 = blockIdx.x * 128;   // bd

    float acc[2][8][4] = {};

    #pragma unroll
    for (int s = 0; s < 2; s++) {
        uint32_t sb = smem_u32(smem + s * STAGEF);
        load_tile(sb,             g_outer, m0, K2, s * BK);
        load_tile(sb + TILEF * 4, g_Wt,    0,  K2, s * BK);
        CP_ASYNC_COMMIT();
    }

    const int NCH = K2 / BK;   // 32
    for (int i = 0; i < NCH; i++) {
        if (i == NCH - 1) { CP_ASYNC_WAIT(0); } else { CP_ASYNC_WAIT(1); }
        __syncthreads();
        if (i + 2 < NCH) {
            uint32_t sb = smem_u32(smem + ((i + 2) % NSTAGE) * STAGEF);
            load_tile(sb,             g_outer, m0, K2, (i + 2) * BK);
            load_tile(sb + TILEF * 4, g_Wt,    0,  K2, (i + 2) * BK);
            CP_ASYNC_COMMIT();
        }
        const float* As = smem + (i % NSTAGE) * STAGEF;
        const float* Bs = As + TILEF;
        mma_chunk(As, Bs, wm, wn, lane, acc);
    }

    const int lr = lane >> 2, lc = lane & 3;
    #pragma unroll
    for (int mi = 0; mi < 2; mi++) {
        const int m = m0 + wm * 32 + mi * 16 + lr;
        const float rn0 = 1.0f / (1e-3f + g_norm[m]);
        const float rn1 = 1.0f / (1e-3f + g_norm[m + 8]);
        #pragma unroll
        for (int ni = 0; ni < 8; ni++) {
            const int f = wn * 64 + ni * 8 + 2 * lc;
            const float b0 = __ldg(bias + f), b1 = __ldg(bias + f + 1);
            float2 v0 = { (acc[mi][ni][0] + b0) * rn0, (acc[mi][ni][1] + b1) * rn0 };
            float2 v1 = { (acc[mi][ni][2] + b0) * rn1, (acc[mi][ni][3] + b1) * rn1 };
            __stcs(reinterpret_cast<float2*>(out + (size_t)m * C_OUT + f), v0);
            __stcs(reinterpret_cast<float2*>(out + (size_t)(m + 8) * C_OUT + f), v1);
        }
    }
}

// ============================================================================
// Launch
// ============================================================================
extern "C" void kernel_launch(void* const* d_in, const int* in_sizes, int n_in,
                              void* d_out, int out_size)
{
    const float* msa   = (const float*)d_in[0];
    const float* mask  = (const float*)d_in[1];
    const float* gamma = (const float*)d_in[2];
    const float* beta  = (const float*)d_in[3];
    const float* wl    = (const float*)d_in[4];
    const float* wr    = (const float*)d_in[5];
    const float* ow    = (const float*)d_in[6];
    const float* ob    = (const float*)d_in[7];
    float* out = (float*)d_out;

    cudaFuncSetAttribute(gemm1_kernel,
                         cudaFuncAttributeMaxDynamicSharedMemorySize, GSMEM);
    cudaFuncSetAttribute(gemm2_kernel,
                         cudaFuncAttributeMaxDynamicSharedMemorySize, GSMEM);

    ln_proj_kernel<<<dim3(S_DIM / 128, R_DIM), 128>>>(msa, mask, gamma, beta, wl, wr);
    wt_prep_kernel<<<(C_OUT * K2) / 256, 256>>>(ow);
    norm_kernel<<<R_DIM / 8, R_DIM>>>(mask);
    gemm1_kernel<<<dim3(M1 / 128, M1 / 128), 256, GSMEM>>>();
    gemm2_kernel<<<M2 / 128, 256, GSMEM>>>(out, ob);
}

// round 14
// speedup vs baseline: 1.1137x; 1.0861x over previous
#include <cuda_runtime.h>
#include <cstdint>
#include <cstddef>

// ============================================================================
// Problem dims
// ============================================================================
#define S_DIM   512
#define R_DIM   384
#define C_MSA   64
#define C_OUTER 32
#define C_OUT   128

#define M1 (R_DIM * C_OUTER)       // 12288
#define K1 S_DIM                   // 512
#define M2 (R_DIM * R_DIM)         // 147456
#define K2 (C_OUTER * C_OUTER)     // 1024

// ============================================================================
// Device-global scratch (allocation-free per harness rules)
// ============================================================================
__device__ float g_leftT [(size_t)M1 * K1];     // [(r*32+c), s] tf32-rounded
__device__ float g_rightT[(size_t)M1 * K1];     // [(r*32+e), s] tf32-rounded
__device__ float g_outer [(size_t)M2 * K2];     // [(b*384+d), c*32+e] tf32-rounded
__device__ float g_Wt    [(size_t)C_OUT * K2];  // [f, c*32+e] tf32-rounded
__device__ float g_norm  [(size_t)R_DIM * R_DIM];

// ============================================================================
// Helpers
// ============================================================================
__device__ __forceinline__ uint32_t smem_u32(const void* p) {
    uint32_t a;
    asm("{ .reg .u64 t; cvta.to.shared.u64 t, %1; cvt.u32.u64 %0, t; }"
        : "=r"(a) : "l"(p));
    return a;
}

// tf32 round-to-nearest: .b32 destination (returns bit pattern)
__device__ __forceinline__ uint32_t tf32_bits(float x) {
    uint32_t r;
    asm("cvt.rna.tf32.f32 %0, %1;" : "=r"(r) : "f"(x));
    return r;
}
__device__ __forceinline__ float rn_tf32(float x) {
    return __uint_as_float(tf32_bits(x));
}

__device__ __forceinline__ void cp16(uint32_t dst_smem, const void* src) {
    asm volatile("cp.async.cg.shared.global [%0], [%1], 16;"
                 :: "r"(dst_smem), "l"(src) : "memory");
}
#define CP_ASYNC_COMMIT() asm volatile("cp.async.commit_group;" ::: "memory")
#define CP_ASYNC_WAIT(n)  asm volatile("cp.async.wait_group %0;" :: "n"(n) : "memory")

// mma.sync m16n8k8 tf32: D += A*B, A row-major 16x8(K), B col-major 8(K)x8
#define MMA_TF32(d, a, b) \
    asm volatile( \
        "mma.sync.aligned.m16n8k8.row.col.f32.tf32.tf32.f32 " \
        "{%0,%1,%2,%3}, {%4,%5,%6,%7}, {%8,%9}, {%0,%1,%2,%3};" \
        : "+f"((d)[0]), "+f"((d)[1]), "+f"((d)[2]), "+f"((d)[3]) \
        : "r"((a)[0]), "r"((a)[1]), "r"((a)[2]), "r"((a)[3]), \
          "r"((b)[0]), "r"((b)[1]))

__device__ __forceinline__ uint32_t f2u(float x) { return __float_as_uint(x); }

// ============================================================================
// Kernel: LayerNorm + projections + mask -> leftT/rightT (K-major tf32)
// grid (4, 384), block 128
// ============================================================================
__global__ __launch_bounds__(128)
void ln_proj_kernel(const float* __restrict__ msa, const float* __restrict__ mask,
                    const float* __restrict__ gamma, const float* __restrict__ beta,
                    const float* __restrict__ wl, const float* __restrict__ wr)
{
    __shared__ float s_wl[C_OUTER][C_MSA];
    __shared__ float s_wr[C_OUTER][C_MSA];
    __shared__ float s_g[C_MSA], s_b[C_MSA];

    const int t = threadIdx.x;
    for (int i = t; i < C_OUTER * C_MSA; i += 128) {
        s_wl[i >> 6][i & 63] = wl[i];
        s_wr[i >> 6][i & 63] = wr[i];
    }
    if (t < C_MSA) { s_g[t] = gamma[t]; s_b[t] = beta[t]; }
    __syncthreads();

    const int r = blockIdx.y;
    const int s = blockIdx.x * 128 + t;

    const float* mrow = msa + ((size_t)s * R_DIM + r) * C_MSA;
    float x[C_MSA];
    #pragma unroll
    for (int i = 0; i < C_MSA / 4; i++) {
        float4 v = reinterpret_cast<const float4*>(mrow)[i];
        x[4*i+0] = v.x; x[4*i+1] = v.y; x[4*i+2] = v.z; x[4*i+3] = v.w;
    }
    float s1 = 0.f, s2 = 0.f;
    #pragma unroll
    for (int c = 0; c < C_MSA; c++) { s1 += x[c]; s2 += x[c] * x[c]; }
    const float mu = s1 * (1.0f / C_MSA);
    const float var = s2 * (1.0f / C_MSA) - mu * mu;
    const float rs = rsqrtf(var + 1e-5f);
    const float mk = mask[(size_t)s * R_DIM + r];
    #pragma unroll
    for (int c = 0; c < C_MSA; c++)
        x[c] = ((x[c] - mu) * rs * s_g[c] + s_b[c]) * mk;  // fold mask

    for (int o = 0; o < C_OUTER; o++) {
        float dl = 0.f, dr = 0.f;
        #pragma unroll
        for (int c = 0; c < C_MSA; c++) {
            dl += x[c] * s_wl[o][c];
            dr += x[c] * s_wr[o][c];
        }
        g_leftT [((size_t)(r * C_OUTER + o)) * K1 + s] = rn_tf32(dl);
        g_rightT[((size_t)(r * C_OUTER + o)) * K1 + s] = rn_tf32(dr);
    }
}

// ============================================================================
// Kernel: transpose/round output_w [c][e][f] -> Wt [f][c*32+e]
// ============================================================================
__global__ __launch_bounds__(256)
void wt_prep_kernel(const float* __restrict__ ow)
{
    int idx = blockIdx.x * 256 + threadIdx.x;       // f-major linear
    int f = idx >> 10, ce = idx & 1023;
    g_Wt[idx] = rn_tf32(ow[(size_t)ce * C_OUT + f]);
}

// ============================================================================
// Kernel: norm[b][d] = sum_s mask[s][b] * mask[s][d]
// ============================================================================
__global__ __launch_bounds__(384)
void norm_kernel(const float* __restrict__ mask)
{
    __shared__ float rowv[R_DIM];
    const int t = threadIdx.x;
    const int b0 = blockIdx.x * 8;
    float acc[8] = {0, 0, 0, 0, 0, 0, 0, 0};
    for (int s = 0; s < S_DIM; s++) {
        __syncthreads();
        rowv[t] = mask[(size_t)s * R_DIM + t];
        __syncthreads();
        const float md = rowv[t];
        #pragma unroll
        for (int j = 0; j < 8; j++) acc[j] += rowv[b0 + j] * md;
    }
    #pragma unroll
    for (int j = 0; j < 8; j++)
        g_norm[(size_t)(b0 + j) * R_DIM + t] = acc[j];
}

// ============================================================================
// GEMM tile config: BM=BN=128, BK=32, 256 thr = 8 warps (4M x 2N),
// warp tile 32x64 (mi=2, ni=8).  3-stage cp.async pipeline, ONE sync/chunk,
// loads issued AFTER compute (R13 A/B test: before-compute costs ~10%).
// smem rows padded to 36 floats (conflict-free fragment LDS).
// ============================================================================
#define BK        32
#define ROWF      36
#define TILEF     (128 * ROWF)                 // 4608 floats per tile
#define STAGEF    (2 * TILEF)                  // A + B per stage
#define NSTAGE    3
#define GSMEM     (NSTAGE * STAGEF * 4)        // 110592 bytes

// load one 128x32 tile (row-major K) from gbase[(row0+row)*ldk + kof ..]
__device__ __forceinline__ void load_tile(uint32_t sbuf, const float* gbase,
                                          int row0, int ldk, int kof)
{
    const int tid = threadIdx.x;
    #pragma unroll
    for (int k = 0; k < 4; k++) {
        int u = k * 256 + tid;
        int row = u >> 3, seg = u & 7;
        const float* src = gbase + ((size_t)(row0 + row)) * ldk + kof + seg * 4;
        cp16(sbuf + row * 144 + seg * 16, src);
    }
}

// compute one BK chunk: acc[2][8][4] += A_tile x B_tile
__device__ __forceinline__ void mma_chunk(const float* __restrict__ A,
                                          const float* __restrict__ B,
                                          int wm, int wn, int lane,
                                          float acc[2][8][4])
{
    const int lr = lane >> 2;      // 0..7
    const int lc = lane & 3;       // 0..3
    #pragma unroll
    for (int kk = 0; kk < 4; kk++) {
        const int c0 = kk * 8 + lc;
        uint32_t a[2][4], b[8][2];
        #pragma unroll
        for (int mi = 0; mi < 2; mi++) {
            const int r0 = wm * 32 + mi * 16 + lr;
            a[mi][0] = f2u(A[r0 * ROWF + c0]);
            a[mi][1] = f2u(A[(r0 + 8) * ROWF + c0]);
            a[mi][2] = f2u(A[r0 * ROWF + c0 + 4]);
            a[mi][3] = f2u(A[(r0 + 8) * ROWF + c0 + 4]);
        }
        #pragma unroll
        for (int ni = 0; ni < 8; ni++) {
            const int rb = wn * 64 + ni * 8 + lr;
            b[ni][0] = f2u(B[rb * ROWF + c0]);
            b[ni][1] = f2u(B[rb * ROWF + c0 + 4]);
        }
        #pragma unroll
        for (int mi = 0; mi < 2; mi++)
            #pragma unroll
            for (int ni = 0; ni < 8; ni++)
                MMA_TF32(acc[mi][ni], a[mi], b[ni]);
    }
}

// ============================================================================
// GEMM1: outer = leftT (12288x512) x rightT^T (12288x512) -> scatter
// grid (96, 96), block 256
// ============================================================================
__global__ __launch_bounds__(256, 2)
void gemm1_kernel()
{
    extern __shared__ __align__(16) float smem[];
    const int tid = threadIdx.x;
    const int lane = tid & 31;
    const int wid = tid >> 5;
    const int wm = wid >> 1, wn = wid & 1;
    const int m0 = blockIdx.y * 128;   // bc
    const int n0 = blockIdx.x * 128;   // de

    float acc[2][8][4] = {};

    // Prologue: stages 0,1 in flight
    #pragma unroll
    for (int s = 0; s < 2; s++) {
        uint32_t sb = smem_u32(smem + s * STAGEF);
        load_tile(sb,             g_leftT,  m0, K1, s * BK);
        load_tile(sb + TILEF * 4, g_rightT, n0, K1, s * BK);
        CP_ASYNC_COMMIT();
    }

    const int NCH = K1 / BK;   // 16
    for (int i = 0; i < NCH; i++) {
        if (i == NCH - 1) { CP_ASYNC_WAIT(0); } else { CP_ASYNC_WAIT(1); }
        __syncthreads();
        const float* As = smem + (i % NSTAGE) * STAGEF;
        const float* Bs = As + TILEF;
        mma_chunk(As, Bs, wm, wn, lane, acc);
        // Load chunk i+2 into the buffer computed at iter i-1 (barrier-safe)
        if (i + 2 < NCH) {
            uint32_t sb = smem_u32(smem + ((i + 2) % NSTAGE) * STAGEF);
            load_tile(sb,             g_leftT,  m0, K1, (i + 2) * BK);
            load_tile(sb + TILEF * 4, g_rightT, n0, K1, (i + 2) * BK);
            CP_ASYNC_COMMIT();
        }
    }

    // Epilogue: scatter (bc, de) tile -> outer[(b*384+d)*1024 + c*32+e]
    const int lr = lane >> 2, lc = lane & 3;
    #pragma unroll
    for (int mi = 0; mi < 2; mi++) {
        #pragma unroll
        for (int ni = 0; ni < 8; ni++) {
            const int m = m0 + wm * 32 + mi * 16 + lr;
            const int n = n0 + wn * 64 + ni * 8 + 2 * lc;
            const int b = m >> 5, c = m & 31;
            const int d = n >> 5, e = n & 31;
            float2 v0 = { rn_tf32(acc[mi][ni][0]), rn_tf32(acc[mi][ni][1]) };
            float2 v1 = { rn_tf32(acc[mi][ni][2]), rn_tf32(acc[mi][ni][3]) };
            float* base = g_outer + ((size_t)(b * R_DIM + d)) * K2 + e;
            __stcs(reinterpret_cast<float2*>(base + c * 32), v0);
            __stcs(reinterpret_cast<float2*>(base + (c + 8) * 32), v1);
        }
    }
}

// ============================================================================
// GEMM2: act = outer (147456x1024) x Wt^T (128x1024), fused bias+norm
// grid 1152, block 256
// ============================================================================
__global__ __launch_bounds__(256, 2)
void gemm2_kernel(float* __restrict__ out, const float* __restrict__ bias)
{
    extern __shared__ __align__(16) float smem[];
    const int tid = threadIdx.x;
    const int lane = tid & 31;
    const int wid = tid >> 5;
    const int wm = wid >> 1, wn = wid & 1;
    const int m0 = blockIdx.x * 128;   // bd

    float acc[2][8][4] = {};

    #pragma unroll
    for (int s = 0; s < 2; s++) {
        uint32_t sb = smem_u32(smem + s * STAGEF);
        load_tile(sb,             g_outer, m0, K2, s * BK);
        load_tile(sb + TILEF * 4, g_Wt,    0,  K2, s * BK);
        CP_ASYNC_COMMIT();
    }

    const int NCH = K2 / BK;   // 32
    for (int i = 0; i < NCH; i++) {
        if (i == NCH - 1) { CP_ASYNC_WAIT(0); } else { CP_ASYNC_WAIT(1); }
        __syncthreads();
        const float* As = smem + (i % NSTAGE) * STAGEF;
        const float* Bs = As + TILEF;
        mma_chunk(As, Bs, wm, wn, lane, acc);
        if (i + 2 < NCH) {
            uint32_t sb = smem_u32(smem + ((i + 2) % NSTAGE) * STAGEF);
            load_tile(sb,             g_outer, m0, K2, (i + 2) * BK);
            load_tile(sb + TILEF * 4, g_Wt,    0,  K2, (i + 2) * BK);
            CP_ASYNC_COMMIT();
        }
    }

    const int lr = lane >> 2, lc = lane & 3;
    #pragma unroll
    for (int mi = 0; mi < 2; mi++) {
        const int m = m0 + wm * 32 + mi * 16 + lr;
        const float rn0 = 1.0f / (1e-3f + g_norm[m]);
        const float rn1 = 1.0f / (1e-3f + g_norm[m + 8]);
        #pragma unroll
        for (int ni = 0; ni < 8; ni++) {
            const int f = wn * 64 + ni * 8 + 2 * lc;
            const float b0 = __ldg(bias + f), b1 = __ldg(bias + f + 1);
            float2 v0 = { (acc[mi][ni][0] + b0) * rn0, (acc[mi][ni][1] + b1) * rn0 };
            float2 v1 = { (acc[mi][ni][2] + b0) * rn1, (acc[mi][ni][3] + b1) * rn1 };
            __stcs(reinterpret_cast<float2*>(out + (size_t)m * C_OUT + f), v0);
            __stcs(reinterpret_cast<float2*>(out + (size_t)(m + 8) * C_OUT + f), v1);
        }
    }
}

// ============================================================================
// Launch
// ============================================================================
extern "C" void kernel_launch(void* const* d_in, const int* in_sizes, int n_in,
                              void* d_out, int out_size)
{
    const float* msa   = (const float*)d_in[0];
    const float* mask  = (const float*)d_in[1];
    const float* gamma = (const float*)d_in[2];
    const float* beta  = (const float*)d_in[3];
    const float* wl    = (const float*)d_in[4];
    const float* wr    = (const float*)d_in[5];
    const float* ow    = (const float*)d_in[6];
    const float* ob    = (const float*)d_in[7];
    float* out = (float*)d_out;

    cudaFuncSetAttribute(gemm1_kernel,
                         cudaFuncAttributeMaxDynamicSharedMemorySize, GSMEM);
    cudaFuncSetAttribute(gemm2_kernel,
                         cudaFuncAttributeMaxDynamicSharedMemorySize, GSMEM);

    ln_proj_kernel<<<dim3(S_DIM / 128, R_DIM), 128>>>(msa, mask, gamma, beta, wl, wr);
    wt_prep_kernel<<<(C_OUT * K2) / 256, 256>>>(ow);
    norm_kernel<<<R_DIM / 8, R_DIM>>>(mask);
    gemm1_kernel<<<dim3(M1 / 128, M1 / 128), 256, GSMEM>>>();
    gemm2_kernel<<<M2 / 128, 256, GSMEM>>>(out, ob);
}

// round 17
// speedup vs baseline: 1.2222x; 1.0975x over previous
#include <cuda_runtime.h>
#include <cuda_fp16.h>
#include <cstdint>
#include <cstddef>

// ============================================================================
// Problem dims
// ============================================================================
#define S_DIM   512
#define R_DIM   384
#define C_MSA   64
#define C_OUTER 32
#define C_OUT   128

#define M1 (R_DIM * C_OUTER)       // 12288
#define K1 S_DIM                   // 512
#define M2 (R_DIM * R_DIM)         // 147456
#define K2 (C_OUTER * C_OUTER)     // 1024

// ============================================================================
// Device-global scratch (allocation-free per harness rules)
// ============================================================================
__device__ float  g_leftT [(size_t)M1 * K1];     // [(r*32+c), s] tf32-rounded
__device__ float  g_rightT[(size_t)M1 * K1];     // [(r*32+e), s] tf32-rounded
__device__ __half g_outer [(size_t)M2 * K2];     // [(b*384+d), c*32+e] fp16
__device__ __half g_Wt    [(size_t)C_OUT * K2];  // [f, c*32+e] fp16
__device__ float  g_norm  [(size_t)R_DIM * R_DIM];

// ============================================================================
// Helpers
// ============================================================================
__device__ __forceinline__ uint32_t smem_u32(const void* p) {
    uint32_t a;
    asm("{ .reg .u64 t; cvta.to.shared.u64 t, %1; cvt.u32.u64 %0, t; }"
        : "=r"(a) : "l"(p));
    return a;
}

// tf32 round-to-nearest: .b32 destination (returns bit pattern)
__device__ __forceinline__ uint32_t tf32_bits(float x) {
    uint32_t r;
    asm("cvt.rna.tf32.f32 %0, %1;" : "=r"(r) : "f"(x));
    return r;
}
__device__ __forceinline__ float rn_tf32(float x) {
    return __uint_as_float(tf32_bits(x));
}

__device__ __forceinline__ void cp16(uint32_t dst_smem, const void* src) {
    asm volatile("cp.async.cg.shared.global [%0], [%1], 16;"
                 :: "r"(dst_smem), "l"(src) : "memory");
}
#define CP_ASYNC_COMMIT() asm volatile("cp.async.commit_group;" ::: "memory")
#define CP_ASYNC_WAIT(n)  asm volatile("cp.async.wait_group %0;" :: "n"(n) : "memory")

// mma.sync m16n8k8 tf32: D += A*B (A row-major, B K-major "col")
#define MMA_TF32(d, a, b) \
    asm volatile( \
        "mma.sync.aligned.m16n8k8.row.col.f32.tf32.tf32.f32 " \
        "{%0,%1,%2,%3}, {%4,%5,%6,%7}, {%8,%9}, {%0,%1,%2,%3};" \
        : "+f"((d)[0]), "+f"((d)[1]), "+f"((d)[2]), "+f"((d)[3]) \
        : "r"((a)[0]), "r"((a)[1]), "r"((a)[2]), "r"((a)[3]), \
          "r"((b)[0]), "r"((b)[1]))

// mma.sync m16n8k16 f16 -> f32 accum
#define MMA_F16(d, a, b) \
    asm volatile( \
        "mma.sync.aligned.m16n8k16.row.col.f32.f16.f16.f32 " \
        "{%0,%1,%2,%3}, {%4,%5,%6,%7}, {%8,%9}, {%0,%1,%2,%3};" \
        : "+f"((d)[0]), "+f"((d)[1]), "+f"((d)[2]), "+f"((d)[3]) \
        : "r"((a)[0]), "r"((a)[1]), "r"((a)[2]), "r"((a)[3]), \
          "r"((b)[0]), "r"((b)[1]))

__device__ __forceinline__ uint32_t f2u(float x) { return __float_as_uint(x); }

// ============================================================================
// Kernel: LayerNorm + projections + mask -> leftT/rightT (K-major tf32)
// grid (4, 384), block 128
// ============================================================================
__global__ __launch_bounds__(128)
void ln_proj_kernel(const float* __restrict__ msa, const float* __restrict__ mask,
                    const float* __restrict__ gamma, const float* __restrict__ beta,
                    const float* __restrict__ wl, const float* __restrict__ wr)
{
    __shared__ float s_wl[C_OUTER][C_MSA];
    __shared__ float s_wr[C_OUTER][C_MSA];
    __shared__ float s_g[C_MSA], s_b[C_MSA];

    const int t = threadIdx.x;
    for (int i = t; i < C_OUTER * C_MSA; i += 128) {
        s_wl[i >> 6][i & 63] = wl[i];
        s_wr[i >> 6][i & 63] = wr[i];
    }
    if (t < C_MSA) { s_g[t] = gamma[t]; s_b[t] = beta[t]; }
    __syncthreads();

    const int r = blockIdx.y;
    const int s = blockIdx.x * 128 + t;

    const float* mrow = msa + ((size_t)s * R_DIM + r) * C_MSA;
    float x[C_MSA];
    #pragma unroll
    for (int i = 0; i < C_MSA / 4; i++) {
        float4 v = reinterpret_cast<const float4*>(mrow)[i];
        x[4*i+0] = v.x; x[4*i+1] = v.y; x[4*i+2] = v.z; x[4*i+3] = v.w;
    }
    float s1 = 0.f, s2 = 0.f;
    #pragma unroll
    for (int c = 0; c < C_MSA; c++) { s1 += x[c]; s2 += x[c] * x[c]; }
    const float mu = s1 * (1.0f / C_MSA);
    const float var = s2 * (1.0f / C_MSA) - mu * mu;
    const float rs = rsqrtf(var + 1e-5f);
    const float mk = mask[(size_t)s * R_DIM + r];
    #pragma unroll
    for (int c = 0; c < C_MSA; c++)
        x[c] = ((x[c] - mu) * rs * s_g[c] + s_b[c]) * mk;  // fold mask

    for (int o = 0; o < C_OUTER; o++) {
        float dl = 0.f, dr = 0.f;
        #pragma unroll
        for (int c = 0; c < C_MSA; c++) {
            dl += x[c] * s_wl[o][c];
            dr += x[c] * s_wr[o][c];
        }
        g_leftT [((size_t)(r * C_OUTER + o)) * K1 + s] = rn_tf32(dl);
        g_rightT[((size_t)(r * C_OUTER + o)) * K1 + s] = rn_tf32(dr);
    }
}

// ============================================================================
// Kernel: transpose output_w [c][e][f] -> Wt [f][c*32+e] (fp16)
// ============================================================================
__global__ __launch_bounds__(256)
void wt_prep_kernel(const float* __restrict__ ow)
{
    int idx = blockIdx.x * 256 + threadIdx.x;       // f-major linear
    int f = idx >> 10, ce = idx & 1023;
    g_Wt[idx] = __float2half_rn(ow[(size_t)ce * C_OUT + f]);
}

// ============================================================================
// Kernel: norm[b][d] = sum_s mask[s][b] * mask[s][d]
// ============================================================================
__global__ __launch_bounds__(384)
void norm_kernel(const float* __restrict__ mask)
{
    __shared__ float rowv[R_DIM];
    const int t = threadIdx.x;
    const int b0 = blockIdx.x * 8;
    float acc[8] = {0, 0, 0, 0, 0, 0, 0, 0};
    for (int s = 0; s < S_DIM; s++) {
        __syncthreads();
        rowv[t] = mask[(size_t)s * R_DIM + t];
        __syncthreads();
        const float md = rowv[t];
        #pragma unroll
        for (int j = 0; j < 8; j++) acc[j] += rowv[b0 + j] * md;
    }
    #pragma unroll
    for (int j = 0; j < 8; j++)
        g_norm[(size_t)(b0 + j) * R_DIM + t] = acc[j];
}

// ============================================================================
// GEMM1 config (R8 optimum): BM=BN=128, BK=32, 8 warps (4M x 2N),
// warp tile 32x64. 3-stage cp.async, ONE sync/chunk, loads AFTER compute.
// ============================================================================
#define BK        32
#define ROWF      36
#define TILEF     (128 * ROWF)                 // 4608 floats per tile
#define STAGEF    (2 * TILEF)                  // A + B per stage
#define NSTAGE    3
#define GSMEM     (NSTAGE * STAGEF * 4)        // 110592 bytes

__device__ __forceinline__ void load_tile(uint32_t sbuf, const float* gbase,
                                          int row0, int ldk, int kof)
{
    const int tid = threadIdx.x;
    #pragma unroll
    for (int k = 0; k < 4; k++) {
        int u = k * 256 + tid;
        int row = u >> 3, seg = u & 7;
        const float* src = gbase + ((size_t)(row0 + row)) * ldk + kof + seg * 4;
        cp16(sbuf + row * 144 + seg * 16, src);
    }
}

__device__ __forceinline__ void mma_chunk(const float* __restrict__ A,
                                          const float* __restrict__ B,
                                          int wm, int wn, int lane,
                                          float acc[2][8][4])
{
    const int lr = lane >> 2;
    const int lc = lane & 3;
    #pragma unroll
    for (int kk = 0; kk < 4; kk++) {
        const int c0 = kk * 8 + lc;
        uint32_t a[2][4], b[8][2];
        #pragma unroll
        for (int mi = 0; mi < 2; mi++) {
            const int r0 = wm * 32 + mi * 16 + lr;
            a[mi][0] = f2u(A[r0 * ROWF + c0]);
            a[mi][1] = f2u(A[(r0 + 8) * ROWF + c0]);
            a[mi][2] = f2u(A[r0 * ROWF + c0 + 4]);
            a[mi][3] = f2u(A[(r0 + 8) * ROWF + c0 + 4]);
        }
        #pragma unroll
        for (int ni = 0; ni < 8; ni++) {
            const int rb = wn * 64 + ni * 8 + lr;
            b[ni][0] = f2u(B[rb * ROWF + c0]);
            b[ni][1] = f2u(B[rb * ROWF + c0 + 4]);
        }
        #pragma unroll
        for (int mi = 0; mi < 2; mi++)
            #pragma unroll
            for (int ni = 0; ni < 8; ni++)
                MMA_TF32(acc[mi][ni], a[mi], b[ni]);
    }
}

// ============================================================================
// GEMM1: outer = leftT (12288x512) x rightT^T -> scatter fp16
// grid (96, 96), block 256
// ============================================================================
__global__ __launch_bounds__(256, 2)
void gemm1_kernel()
{
    extern __shared__ __align__(16) float smem[];
    const int tid = threadIdx.x;
    const int lane = tid & 31;
    const int wid = tid >> 5;
    const int wm = wid >> 1, wn = wid & 1;
    const int m0 = blockIdx.y * 128;   // bc
    const int n0 = blockIdx.x * 128;   // de

    float acc[2][8][4] = {};

    #pragma unroll
    for (int s = 0; s < 2; s++) {
        uint32_t sb = smem_u32(smem + s * STAGEF);
        load_tile(sb,             g_leftT,  m0, K1, s * BK);
        load_tile(sb + TILEF * 4, g_rightT, n0, K1, s * BK);
        CP_ASYNC_COMMIT();
    }

    const int NCH = K1 / BK;   // 16
    for (int i = 0; i < NCH; i++) {
        if (i == NCH - 1) { CP_ASYNC_WAIT(0); } else { CP_ASYNC_WAIT(1); }
        __syncthreads();
        const float* As = smem + (i % NSTAGE) * STAGEF;
        const float* Bs = As + TILEF;
        mma_chunk(As, Bs, wm, wn, lane, acc);
        if (i + 2 < NCH) {
            uint32_t sb = smem_u32(smem + ((i + 2) % NSTAGE) * STAGEF);
            load_tile(sb,             g_leftT,  m0, K1, (i + 2) * BK);
            load_tile(sb + TILEF * 4, g_rightT, n0, K1, (i + 2) * BK);
            CP_ASYNC_COMMIT();
        }
    }

    // Epilogue: scatter (bc, de) tile -> outer[(b*384+d)*1024 + c*32+e], fp16
    const int lr = lane >> 2, lc = lane & 3;
    #pragma unroll
    for (int mi = 0; mi < 2; mi++) {
        #pragma unroll
        for (int ni = 0; ni < 8; ni++) {
            const int m = m0 + wm * 32 + mi * 16 + lr;
            const int n = n0 + wn * 64 + ni * 8 + 2 * lc;
            const int b = m >> 5, c = m & 31;
            const int d = n >> 5, e = n & 31;
            __half2 h0 = __floats2half2_rn(acc[mi][ni][0], acc[mi][ni][1]);
            __half2 h1 = __floats2half2_rn(acc[mi][ni][2], acc[mi][ni][3]);
            __half* base = g_outer + ((size_t)(b * R_DIM + d)) * K2 + e;
            __stcs(reinterpret_cast<uint32_t*>(base + c * 32),
                   *reinterpret_cast<uint32_t*>(&h0));
            __stcs(reinterpret_cast<uint32_t*>(base + (c + 8) * 32),
                   *reinterpret_cast<uint32_t*>(&h1));
        }
    }
}

// ============================================================================
// GEMM2 (fp16): act = outer (147456x1024) x Wt^T (128x1024), bias+norm fused
// Tiles 128x128, BK=32 halves; fp16 m16n8k16. Row stride 40 halves (80 B,
// 20 u32 -> lr*20 mod 32 bank pattern conflict-free).
// ============================================================================
#define HROWU     20                           // uint32 per smem row (40 halves)
#define HTILE_B   (128 * 80)                   // 10240 bytes per tile
#define STAGE2_B  (2 * HTILE_B)                // 20480 bytes per stage
#define G2SMEM    (NSTAGE * STAGE2_B)          // 61440 bytes

__device__ __forceinline__ void load_tile_h(uint32_t sbuf, const __half* gbase,
                                            int row0, int ldk, int kof)
{
    const int tid = threadIdx.x;
    #pragma unroll
    for (int k = 0; k < 2; k++) {
        int u = k * 256 + tid;
        int row = u >> 2, seg = u & 3;
        const __half* src = gbase + ((size_t)(row0 + row)) * ldk + kof + seg * 8;
        cp16(sbuf + row * 80 + seg * 16, src);
    }
}

__device__ __forceinline__ void mma_chunk_h(const uint32_t* __restrict__ A32,
                                            const uint32_t* __restrict__ B32,
                                            int wm, int wn, int lane,
                                            float acc[2][8][4])
{
    const int lr = lane >> 2;
    const int lc = lane & 3;
    #pragma unroll
    for (int kk = 0; kk < 2; kk++) {
        const int ko = kk * 8 + lc;     // u32 offset: kk*16 halves
        uint32_t a[2][4], b[8][2];
        #pragma unroll
        for (int mi = 0; mi < 2; mi++) {
            const int r0 = wm * 32 + mi * 16 + lr;
            a[mi][0] = A32[r0 * HROWU + ko];
            a[mi][1] = A32[(r0 + 8) * HROWU + ko];
            a[mi][2] = A32[r0 * HROWU + ko + 4];
            a[mi][3] = A32[(r0 + 8) * HROWU + ko + 4];
        }
        #pragma unroll
        for (int ni = 0; ni < 8; ni++) {
            const int rb = wn * 64 + ni * 8 + lr;
            b[ni][0] = B32[rb * HROWU + ko];
            b[ni][1] = B32[rb * HROWU + ko + 4];
        }
        #pragma unroll
        for (int mi = 0; mi < 2; mi++)
            #pragma unroll
            for (int ni = 0; ni < 8; ni++)
                MMA_F16(acc[mi][ni], a[mi], b[ni]);
    }
}

__global__ __launch_bounds__(256, 2)
void gemm2_kernel(float* __restrict__ out, const float* __restrict__ bias)
{
    extern __shared__ __align__(16) char smem2[];
    const int tid = threadIdx.x;
    const int lane = tid & 31;
    const int wid = tid >> 5;
    const int wm = wid >> 1, wn = wid & 1;
    const int m0 = blockIdx.x * 128;   // bd

    float acc[2][8][4] = {};

    #pragma unroll
    for (int s = 0; s < 2; s++) {
        uint32_t sb = smem_u32(smem2 + s * STAGE2_B);
        load_tile_h(sb,           g_outer, m0, K2, s * BK);
        load_tile_h(sb + HTILE_B, g_Wt,    0,  K2, s * BK);
        CP_ASYNC_COMMIT();
    }

    const int NCH = K2 / BK;   // 32
    for (int i = 0; i < NCH; i++) {
        if (i == NCH - 1) { CP_ASYNC_WAIT(0); } else { CP_ASYNC_WAIT(1); }
        __syncthreads();
        const uint32_t* As32 =
            reinterpret_cast<const uint32_t*>(smem2 + (i % NSTAGE) * STAGE2_B);
        const uint32_t* Bs32 = As32 + HTILE_B / 4;
        mma_chunk_h(As32, Bs32, wm, wn, lane, acc);
        if (i + 2 < NCH) {
            uint32_t sb = smem_u32(smem2 + ((i + 2) % NSTAGE) * STAGE2_B);
            load_tile_h(sb,           g_outer, m0, K2, (i + 2) * BK);
            load_tile_h(sb + HTILE_B, g_Wt,    0,  K2, (i + 2) * BK);
            CP_ASYNC_COMMIT();
        }
    }

    const int lr = lane >> 2, lc = lane & 3;
    #pragma unroll
    for (int mi = 0; mi < 2; mi++) {
        const int m = m0 + wm * 32 + mi * 16 + lr;
        const float rn0 = 1.0f / (1e-3f + g_norm[m]);
        const float rn1 = 1.0f / (1e-3f + g_norm[m + 8]);
        #pragma unroll
        for (int ni = 0; ni < 8; ni++) {
            const int f = wn * 64 + ni * 8 + 2 * lc;
            const float b0 = __ldg(bias + f), b1 = __ldg(bias + f + 1);
            float2 v0 = { (acc[mi][ni][0] + b0) * rn0, (acc[mi][ni][1] + b1) * rn0 };
            float2 v1 = { (acc[mi][ni][2] + b0) * rn1, (acc[mi][ni][3] + b1) * rn1 };
            __stcs(reinterpret_cast<float2*>(out + (size_t)m * C_OUT + f), v0);
            __stcs(reinterpret_cast<float2*>(out + (size_t)(m + 8) * C_OUT + f), v1);
        }
    }
}

// ============================================================================
// Launch
// ============================================================================
extern "C" void kernel_launch(void* const* d_in, const int* in_sizes, int n_in,
                              void* d_out, int out_size)
{
    const float* msa   = (const float*)d_in[0];
    const float* mask  = (const float*)d_in[1];
    const float* gamma = (const float*)d_in[2];
    const float* beta  = (const float*)d_in[3];
    const float* wl    = (const float*)d_in[4];
    const float* wr    = (const float*)d_in[5];
    const float* ow    = (const float*)d_in[6];
    const float* ob    = (const float*)d_in[7];
    float* out = (float*)d_out;

    cudaFuncSetAttribute(gemm1_kernel,
                         cudaFuncAttributeMaxDynamicSharedMemorySize, GSMEM);
    cudaFuncSetAttribute(gemm2_kernel,
                         cudaFuncAttributeMaxDynamicSharedMemorySize, G2SMEM);

    ln_proj_kernel<<<dim3(S_DIM / 128, R_DIM), 128>>>(msa, mask, gamma, beta, wl, wr);
    wt_prep_kernel<<<(C_OUT * K2) / 256, 256>>>(ow);
    norm_kernel<<<R_DIM / 8, R_DIM>>>(mask);
    gemm1_kernel<<<dim3(M1 / 128, M1 / 128), 256, GSMEM>>>();
    gemm2_kernel<<<M2 / 128, 256, G2SMEM>>>(out, ob);
}